// round 4
// baseline (speedup 1.0000x reference)
#include <cuda_runtime.h>

#define NB 4
#define NS 2048
#define ND 128
#define NDL 16
#define NTOP 8
#define TQ 16
#define NSEG (NS / TQ)   // 128 q-segments (one per fused block)

// ---- scratch (device globals; no allocation allowed) ----
__device__ float g_qlow[NB * NS * NDL];
__device__ float g_klow[NB * NS * NDL];
__device__ float g_sh[NB * NS];
__device__ float g_E[(size_t)NB * NS * NS];          // 64 MB exp(corrected scores)
__device__ float g_psum[NSEG * NB * NS];             // 4 MB column partial sums
__device__ float g_cinv[NB * NS];

__device__ __forceinline__ float neg_inf() { return __int_as_float(0xff800000u); }

// ---- packed f32x2 helpers (FFMA2 path; ptxas won't emit this from C++) ----
__device__ __forceinline__ unsigned long long pack2(float lo, float hi) {
    unsigned long long r;
    asm("mov.b64 %0, {%1, %2};" : "=l"(r) : "f"(lo), "f"(hi));
    return r;
}
__device__ __forceinline__ void unpack2(unsigned long long v, float& lo, float& hi) {
    asm("mov.b64 {%0, %1}, %2;" : "=f"(lo), "=f"(hi) : "l"(v));
}
__device__ __forceinline__ void fma2(unsigned long long& acc,
                                     unsigned long long a, unsigned long long b) {
    asm("fma.rn.f32x2 %0, %1, %2, %0;" : "+l"(acc) : "l"(a), "l"(b));
}

// ============================================================
// K1: low/high projections + per-(b,k) correction scalar sh
// ============================================================
__global__ void __launch_bounds__(64) k_proj(
    const float* __restrict__ Q, const float* __restrict__ K,
    const float* __restrict__ Wql, const float* __restrict__ bql,
    const float* __restrict__ Wkl, const float* __restrict__ bkl,
    const float* __restrict__ Wqh, const float* __restrict__ bqh,
    const float* __restrict__ Wkh, const float* __restrict__ bkh)
{
    int row = blockIdx.x;          // b*NS + i
    int t = threadIdx.x;
    __shared__ float qr[ND];
    __shared__ float kr[ND];
    __shared__ float qh[NDL];
    __shared__ float kh[NDL];

    qr[t]      = Q[(size_t)row * ND + t];
    qr[t + 64] = Q[(size_t)row * ND + t + 64];
    kr[t]      = K[(size_t)row * ND + t];
    kr[t + 64] = K[(size_t)row * ND + t + 64];
    __syncthreads();

    int g = t >> 4, j = t & 15;
    if (g == 0) {
        float a = bql[j];
        #pragma unroll 8
        for (int e = 0; e < ND; e++) a += qr[e] * Wql[e * NDL + j];
        g_qlow[(size_t)row * NDL + j] = a;
    } else if (g == 1) {
        float a = bkl[j];
        #pragma unroll 8
        for (int e = 0; e < ND; e++) a += kr[e] * Wkl[e * NDL + j];
        g_klow[(size_t)row * NDL + j] = a;
    } else if (g == 2) {
        float a = bqh[j];
        #pragma unroll 8
        for (int e = 0; e < ND; e++) a += qr[e] * Wqh[e * NDL + j];
        qh[j] = a;
    } else {
        float a = bkh[j];
        #pragma unroll 8
        for (int e = 0; e < ND; e++) a += kr[e] * Wkh[e * NDL + j];
        kh[j] = a;
    }
    __syncthreads();

    if (t == 0) {
        float s = 0.f;
        #pragma unroll
        for (int j2 = 0; j2 < NDL; j2++) s += qh[j2] * kh[j2];
        g_sh[row] = 0.25f * s;    // scale = 1/sqrt(16)
    }
}

// ============================================================
// K2 fused: scores + per-row top-8 + correction + exp + E-write
//           + per-block column partial sums
// block = 512 threads, TQ=16 q rows x all 2048 k; warp w owns row w.
// dynamic smem: S[16][2048] | ks[256][20] | qs[16][16] | vls[256]
// ============================================================
#define SM_S    0
#define SM_KS   (TQ * NS)                 // 32768
#define SM_QS   (SM_KS + 256 * 20)        // 37888
#define SM_VLS  (SM_QS + TQ * NDL)        // 38144
#define SM_FUSED_BYTES ((SM_VLS + 256) * 4)

__global__ void __launch_bounds__(512) k_fused(const int* __restrict__ VL)
{
    extern __shared__ float sm[];
    float* S  = sm + SM_S;
    float* ks = sm + SM_KS;
    float* qs = sm + SM_QS;
    int*  vls = (int*)(sm + SM_VLS);

    int b  = blockIdx.y;
    int q0 = blockIdx.x * TQ;
    int t  = threadIdx.x;
    int lane = t & 31;
    int w    = t >> 5;          // warp = local q row (0..15)
    int myq  = q0 + w;

    // q_low tile [16][16]
    if (t < (TQ * NDL) / 4)
        ((float4*)qs)[t] = ((const float4*)(g_qlow + ((size_t)b * NS + q0) * NDL))[t];
    __syncthreads();

    float qv[NDL];
    #pragma unroll
    for (int u = 0; u < NDL; u++) qv[u] = qs[w * NDL + u];   // broadcast

    // ---- phase 1: scores into smem S ----
    for (int kc = 0; kc < NS; kc += 256) {
        __syncthreads();   // protect ks/vls reuse
        {
            const float4* src = (const float4*)(g_klow + ((size_t)b * NS + kc) * NDL);
            #pragma unroll
            for (int u = 0; u < 2; u++) {
                int p = t + u * 512;                 // float4 id: k=p>>2, e-grp=p&3
                float4 v = src[p];
                *(float4*)&ks[(p >> 2) * 20 + (p & 3) * 4] = v;
            }
        }
        if (t < 256) {
            int vlc = VL[b * NS + kc + t];
            vlc = vlc < 0 ? 0 : (vlc > NS - 1 ? NS - 1 : vlc);
            vls[t] = vlc;
        }
        __syncthreads();

        #pragma unroll
        for (int i = 0; i < 8; i++) {
            int kl = lane + 32 * i;
            const float* krow = &ks[kl * 20];
            float a = 0.f;
            #pragma unroll
            for (int u = 0; u < 4; u++) {
                float4 kv = *(const float4*)&krow[u * 4];
                a += qv[u*4+0]*kv.x + qv[u*4+1]*kv.y + qv[u*4+2]*kv.z + qv[u*4+3]*kv.w;
            }
            a *= 0.25f;
            if (vls[kl] == myq) a += -1e9f;
            S[w * NS + kc + kl] = a;
        }
    }
    // warp w wrote row w entirely -> no block sync needed before per-warp topk

    // ---- phase 2: per-warp top-8 over own row (exact (v desc, idx asc)) ----
    float* Srow = S + w * NS;
    float rv[NTOP]; int ri[NTOP];
    #pragma unroll
    for (int j = 0; j < NTOP; j++) { rv[j] = neg_inf(); ri[j] = 0x7fffffff; }

    #pragma unroll 4
    for (int i = 0; i < 64; i++) {
        int k = lane + 32 * i;
        float v = Srow[k];
        if (v > rv[7] || (v == rv[7] && k < ri[7])) {
            bool pj = true;                         // better than slot 7 (entry)
            #pragma unroll
            for (int j = 7; j >= 1; j--) {
                bool pjm1 = (v > rv[j-1]) || (v == rv[j-1] && k < ri[j-1]);
                if (pj) {
                    rv[j] = pjm1 ? rv[j-1] : v;
                    ri[j] = pjm1 ? ri[j-1] : k;
                }
                pj = pjm1;
            }
            if (pj) { rv[0] = v; ri[0] = k; }
        }
    }

    int tsel[NTOP];
    #pragma unroll
    for (int r = 0; r < NTOP; r++) {
        float m = rv[0]; int mi = ri[0];
        #pragma unroll
        for (int o = 16; o > 0; o >>= 1) {
            float ov = __shfl_xor_sync(0xffffffffu, m, o);
            int   oi = __shfl_xor_sync(0xffffffffu, mi, o);
            if (ov > m || (ov == m && oi < mi)) { m = ov; mi = oi; }
        }
        tsel[r] = mi;                     // uniform across warp
        if (ri[0] == mi) {                // unique owner (indices distinct)
            #pragma unroll
            for (int j = 0; j < NTOP - 1; j++) { rv[j] = rv[j+1]; ri[j] = ri[j+1]; }
            rv[NTOP-1] = neg_inf(); ri[NTOP-1] = 0x7fffffff;
        }
    }

    // scatter corrections: lane r handles tsel[r]
    int myidx = 0;
    #pragma unroll
    for (int r = 0; r < NTOP; r++) if (lane == r) myidx = tsel[r];
    if (lane < NTOP)
        Srow[myidx] = g_sh[b * NS + myidx];
    __syncthreads();

    // ---- phase 3: exp + E write + column partial sums ----
    {
        int k4 = t * 4;                               // 512*4 = 2048
        float* Eb = g_E + ((size_t)b * NS + q0) * NS + k4;
        float4 acc = make_float4(0.f, 0.f, 0.f, 0.f);
        #pragma unroll
        for (int r = 0; r < TQ; r++) {
            float4 v = *(const float4*)&S[r * NS + k4];
            float4 e;
            e.x = __expf(v.x); e.y = __expf(v.y);
            e.z = __expf(v.z); e.w = __expf(v.w);
            acc.x += e.x; acc.y += e.y; acc.z += e.z; acc.w += e.w;
            *(float4*)(Eb + (size_t)r * NS) = e;
        }
        *(float4*)&g_psum[((size_t)blockIdx.x * NB + b) * NS + k4] = acc;
    }
}

// ============================================================
// K3: combine 128 deterministic segments -> 1/colsum
// ============================================================
__global__ void __launch_bounds__(256) k_colfin()
{
    int i = blockIdx.x * 256 + threadIdx.x;   // b*NS + k
    float s = 0.f;
    #pragma unroll 8
    for (int seg = 0; seg < NSEG; seg++)
        s += g_psum[(size_t)seg * (NB * NS) + i];
    g_cinv[i] = 1.0f / s;
}

// ============================================================
// K4: out[b,q,:] = sum_k E[q,k]*cinv[k] * V[b,k,:]   (dup-packed FFMA2)
// block = 256 threads, tile 64 q x 128 d, K-chunks of 32
// As stored duplicate-packed (a,a) as 64-bit so inner loop has zero MOVs
// ============================================================
__global__ void __launch_bounds__(256) k_out(const float* __restrict__ V,
                                             float* __restrict__ Out)
{
    __shared__ unsigned long long As2[64][32];       // 16 KB
    __shared__ __align__(16) float Vs[32][128];      // 16 KB

    int b  = blockIdx.y;
    int q0 = blockIdx.x * 64;
    int t  = threadIdx.x;
    int tx = t & 31;     // d group: d = tx*4
    int ty = t >> 5;     // q group: q = q0 + ty*8 + qq

    const float* Eb = g_E + (size_t)b * NS * NS;
    const float* ci = g_cinv + b * NS;
    const float* Vb = V + (size_t)b * NS * ND;

    unsigned long long acc2[8][2];
    #pragma unroll
    for (int i = 0; i < 8; i++) { acc2[i][0] = 0ull; acc2[i][1] = 0ull; }

    for (int k0 = 0; k0 < NS; k0 += 32) {
        __syncthreads();
        // A tile 64x32: (E*cinv) dup-packed on load (512 float4, 2/thread)
        #pragma unroll
        for (int u = 0; u < 2; u++) {
            int p = t + u * 256;
            int row = p >> 3, colg = p & 7;
            int kk = k0 + colg * 4;
            float4 e4 = *(const float4*)&Eb[(size_t)(q0 + row) * NS + kk];
            float4 c4 = *(const float4*)&ci[kk];
            float a0 = e4.x * c4.x, a1 = e4.y * c4.y;
            float a2 = e4.z * c4.z, a3 = e4.w * c4.w;
            As2[row][colg * 4 + 0] = pack2(a0, a0);
            As2[row][colg * 4 + 1] = pack2(a1, a1);
            As2[row][colg * 4 + 2] = pack2(a2, a2);
            As2[row][colg * 4 + 3] = pack2(a3, a3);
        }
        // V tile 32x128 (1024 float4, 4/thread)
        #pragma unroll
        for (int u = 0; u < 4; u++) {
            int p = t + u * 256;
            int row = p >> 5, colg = p & 31;
            *(float4*)&Vs[row][colg * 4] =
                *(const float4*)&Vb[(size_t)(k0 + row) * ND + colg * 4];
        }
        __syncthreads();

        #pragma unroll
        for (int kk = 0; kk < 32; kk++) {
            ulonglong2 vv = *(const ulonglong2*)&Vs[kk][tx * 4];
            #pragma unroll
            for (int qq = 0; qq < 8; qq++) {
                unsigned long long aa = As2[ty * 8 + qq][kk];   // LDS64 broadcast
                fma2(acc2[qq][0], aa, vv.x);
                fma2(acc2[qq][1], aa, vv.y);
            }
        }
    }

    #pragma unroll
    for (int qq = 0; qq < 8; qq++) {
        float4 o;
        unpack2(acc2[qq][0], o.x, o.y);
        unpack2(acc2[qq][1], o.z, o.w);
        *(float4*)&Out[(size_t)((b * NS) + q0 + ty * 8 + qq) * ND + tx * 4] = o;
    }
}

// ============================================================
extern "C" void kernel_launch(void* const* d_in, const int* in_sizes, int n_in,
                              void* d_out, int out_size)
{
    const float* Q   = (const float*)d_in[0];
    const float* K   = (const float*)d_in[1];
    const float* V   = (const float*)d_in[2];
    const int*   VL  = (const int*)d_in[3];
    const float* Wql = (const float*)d_in[4];
    const float* bql = (const float*)d_in[5];
    const float* Wkl = (const float*)d_in[6];
    const float* bkl = (const float*)d_in[7];
    const float* Wqh = (const float*)d_in[8];
    const float* bqh = (const float*)d_in[9];
    const float* Wkh = (const float*)d_in[10];
    const float* bkh = (const float*)d_in[11];
    float* out = (float*)d_out;

    // >48KB dynamic smem opt-in (not a stream op; capture-safe, idempotent)
    cudaFuncSetAttribute(k_fused, cudaFuncAttributeMaxDynamicSharedMemorySize,
                         SM_FUSED_BYTES);

    k_proj<<<NB * NS, 64>>>(Q, K, Wql, bql, Wkl, bkl, Wqh, bqh, Wkh, bkh);

    dim3 g2(NS / TQ, NB);
    k_fused<<<g2, 512, SM_FUSED_BYTES>>>(VL);

    k_colfin<<<(NB * NS) / 256, 256>>>();

    dim3 g4(NS / 64, NB);
    k_out<<<g4, 256>>>(V, out);
}

// round 5
// speedup vs baseline: 1.2672x; 1.2672x over previous
#include <cuda_runtime.h>
#include <cstdint>

#define NB 4
#define NS 2048
#define ND 128
#define NDL 16
#define NTOP 8

#define NSEG 64
#define QSEG (NS / NSEG)   // 32

typedef unsigned long long ull;

// ---- scratch (device globals; no allocation allowed) ----
__device__ float g_qlow[NB * NS * NDL];
__device__ float g_klow[NB * NS * NDL];
__device__ float g_sh[NB * NS];
__device__ float g_S[(size_t)NB * NS * NS];          // 64 MB corrected scores
__device__ float g_psum[NSEG * NB * NS];             // 2 MB column partial sums
__device__ float g_cinv[NB * NS];
__device__ float g_Vp[NB * NS * ND];                 // cinv-prescaled V

__device__ __forceinline__ float neg_inf() { return __int_as_float(0xff800000u); }

// ---- packed f32x2 helpers (FFMA2 path; ptxas won't emit this from C++) ----
__device__ __forceinline__ ull pack2(float lo, float hi) {
    ull r;
    asm("mov.b64 %0, {%1, %2};" : "=l"(r) : "f"(lo), "f"(hi));
    return r;
}
__device__ __forceinline__ ull pack2dup(float v) {
    ull r;
    asm("mov.b64 %0, {%1, %1};" : "=l"(r) : "f"(v));
    return r;
}
__device__ __forceinline__ void unpack2(ull v, float& lo, float& hi) {
    asm("mov.b64 {%0, %1}, %2;" : "=f"(lo), "=f"(hi) : "l"(v));
}
__device__ __forceinline__ void fma2(ull& acc, ull a, ull b) {
    asm("fma.rn.f32x2 %0, %1, %2, %0;" : "+l"(acc) : "l"(a), "l"(b));
}

// ---- cp.async helpers ----
__device__ __forceinline__ void cp16(void* s, const void* g) {
    uint32_t sa = (uint32_t)__cvta_generic_to_shared(s);
    asm volatile("cp.async.cg.shared.global [%0], [%1], 16;" :: "r"(sa), "l"(g) : "memory");
}
#define CP_COMMIT() asm volatile("cp.async.commit_group;" ::: "memory")
#define CP_WAIT1()  asm volatile("cp.async.wait_group 1;" ::: "memory")
#define CP_WAIT0()  asm volatile("cp.async.wait_group 0;" ::: "memory")

// ============================================================
// K1: low/high projections + per-(b,k) correction scalar sh
// ============================================================
__global__ void __launch_bounds__(64) k_proj(
    const float* __restrict__ Q, const float* __restrict__ K,
    const float* __restrict__ Wql, const float* __restrict__ bql,
    const float* __restrict__ Wkl, const float* __restrict__ bkl,
    const float* __restrict__ Wqh, const float* __restrict__ bqh,
    const float* __restrict__ Wkh, const float* __restrict__ bkh)
{
    int row = blockIdx.x;          // b*NS + i
    int t = threadIdx.x;
    __shared__ float qr[ND];
    __shared__ float kr[ND];
    __shared__ float qh[NDL];
    __shared__ float kh[NDL];

    qr[t]      = Q[(size_t)row * ND + t];
    qr[t + 64] = Q[(size_t)row * ND + t + 64];
    kr[t]      = K[(size_t)row * ND + t];
    kr[t + 64] = K[(size_t)row * ND + t + 64];
    __syncthreads();

    int g = t >> 4, j = t & 15;
    if (g == 0) {
        float a = bql[j];
        #pragma unroll 8
        for (int e = 0; e < ND; e++) a += qr[e] * Wql[e * NDL + j];
        g_qlow[(size_t)row * NDL + j] = a;
    } else if (g == 1) {
        float a = bkl[j];
        #pragma unroll 8
        for (int e = 0; e < ND; e++) a += kr[e] * Wkl[e * NDL + j];
        g_klow[(size_t)row * NDL + j] = a;
    } else if (g == 2) {
        float a = bqh[j];
        #pragma unroll 8
        for (int e = 0; e < ND; e++) a += qr[e] * Wqh[e * NDL + j];
        qh[j] = a;
    } else {
        float a = bkh[j];
        #pragma unroll 8
        for (int e = 0; e < ND; e++) a += kr[e] * Wkh[e * NDL + j];
        kh[j] = a;
    }
    __syncthreads();

    if (t == 0) {
        float s = 0.f;
        #pragma unroll
        for (int j2 = 0; j2 < NDL; j2++) s += qh[j2] * kh[j2];
        g_sh[row] = 0.25f * s;    // scale = 1/sqrt(16)
    }
}

// ============================================================
// K2a: masked low-rank scores -> g_S  (f32x2 packed: 2 q rows per lane)
// block = 256 threads, tile 32 q x 128 k
// ============================================================
__global__ void __launch_bounds__(256) k_scores(const int* __restrict__ VL)
{
    __shared__ __align__(16) float ks[128][20];
    __shared__ __align__(16) float Ss[32][132];
    __shared__ int vls[128];

    int b  = blockIdx.z;
    int q0 = blockIdx.y * 32;
    int k0 = blockIdx.x * 128;
    int t  = threadIdx.x;

    {
        const float4* src = (const float4*)(g_klow + ((size_t)b * NS + k0) * NDL);
        #pragma unroll
        for (int u = 0; u < 2; u++) {
            int p = t + u * 256;
            float4 v = src[p];
            *(float4*)&ks[p >> 2][(p & 3) * 4] = v;
        }
    }
    if (t < 128) {
        int vlc = VL[b * NS + k0 + t];
        vlc = vlc < 0 ? 0 : (vlc > NS - 1 ? NS - 1 : vlc);
        vls[t] = vlc;
    }
    __syncthreads();

    int tq = t >> 4;             // 0..15
    int kg = t & 15;             // 0..15
    int ql0 = tq * 2;
    int qg0 = q0 + ql0, qg1 = qg0 + 1;

    ull qp2[NDL];
    {
        const float4* qp = (const float4*)(g_qlow + ((size_t)b * NS + qg0) * NDL);
        #pragma unroll
        for (int u = 0; u < 4; u++) {
            float4 v = qp[u];       // row 0
            float4 w = qp[u + 4];   // row 1
            qp2[u * 4 + 0] = pack2(v.x, w.x);
            qp2[u * 4 + 1] = pack2(v.y, w.y);
            qp2[u * 4 + 2] = pack2(v.z, w.z);
            qp2[u * 4 + 3] = pack2(v.w, w.w);
        }
    }

    #pragma unroll
    for (int i = 0; i < 8; i++) {
        int kl = kg + 16 * i;
        ull acc = 0ull;
        #pragma unroll
        for (int u = 0; u < 4; u++) {
            float4 kv = *(const float4*)&ks[kl][u * 4];
            fma2(acc, qp2[u * 4 + 0], pack2dup(kv.x));
            fma2(acc, qp2[u * 4 + 1], pack2dup(kv.y));
            fma2(acc, qp2[u * 4 + 2], pack2dup(kv.z));
            fma2(acc, qp2[u * 4 + 3], pack2dup(kv.w));
        }
        float a0, a1;
        unpack2(acc, a0, a1);
        a0 *= 0.25f; a1 *= 0.25f;
        int vlc = vls[kl];
        if (vlc == qg0) a0 += -1e9f;
        if (vlc == qg1) a1 += -1e9f;
        Ss[ql0][kl]     = a0;
        Ss[ql0 + 1][kl] = a1;
    }
    __syncthreads();

    #pragma unroll
    for (int u = 0; u < 4; u++) {
        int p = t + u * 256;
        int row = p >> 5, cg = p & 31;
        float4 v = *(const float4*)&Ss[row][cg * 4];
        *(float4*)(g_S + ((size_t)b * NS + q0 + row) * NS + k0 + cg * 4) = v;
    }
}

// ============================================================
// K2b: per-row top-8 + scatter sh. One WARP per row, no smem.
// grid (NS/8, NB), block 256 = 8 warps.
// ============================================================
__global__ void __launch_bounds__(256) k_topk()
{
    int b = blockIdx.y;
    int q = blockIdx.x * 8 + (threadIdx.x >> 5);
    int lane = threadIdx.x & 31;
    float* Srow = g_S + ((size_t)b * NS + q) * NS;

    float rv[NTOP]; int ri[NTOP];
    #pragma unroll
    for (int j = 0; j < NTOP; j++) { rv[j] = neg_inf(); ri[j] = 0x7fffffff; }

    // stream 64 values/lane (16 float4, coalesced) through sorted top-8 insert
    #pragma unroll 4
    for (int i = 0; i < 16; i++) {
        int f = lane + i * 32;                 // float4 index
        float4 v4 = *(const float4*)&Srow[f * 4];
        float vv[4] = {v4.x, v4.y, v4.z, v4.w};
        #pragma unroll
        for (int j4 = 0; j4 < 4; j4++) {
            float v = vv[j4];
            int k = f * 4 + j4;
            if (v > rv[7] || (v == rv[7] && k < ri[7])) {
                bool pj = true;
                #pragma unroll
                for (int j = 7; j >= 1; j--) {
                    bool pjm1 = (v > rv[j-1]) || (v == rv[j-1] && k < ri[j-1]);
                    if (pj) {
                        rv[j] = pjm1 ? rv[j-1] : v;
                        ri[j] = pjm1 ? ri[j-1] : k;
                    }
                    pj = pjm1;
                }
                if (pj) { rv[0] = v; ri[0] = k; }
            }
        }
    }

    int tsel[NTOP];
    #pragma unroll
    for (int r = 0; r < NTOP; r++) {
        float m = rv[0]; int mi = ri[0];
        #pragma unroll
        for (int o = 16; o > 0; o >>= 1) {
            float ov = __shfl_xor_sync(0xffffffffu, m, o);
            int   oi = __shfl_xor_sync(0xffffffffu, mi, o);
            if (ov > m || (ov == m && oi < mi)) { m = ov; mi = oi; }
        }
        tsel[r] = mi;
        if (ri[0] == mi) {      // unique owner pops its head
            #pragma unroll
            for (int j = 0; j < NTOP - 1; j++) { rv[j] = rv[j+1]; ri[j] = ri[j+1]; }
            rv[NTOP-1] = neg_inf(); ri[NTOP-1] = 0x7fffffff;
        }
    }

    int myidx = 0;
    #pragma unroll
    for (int r = 0; r < NTOP; r++) if (lane == r) myidx = tsel[r];
    if (lane < NTOP)
        Srow[myidx] = g_sh[b * NS + myidx];
}

// ============================================================
// K3a: partial column sum of exp over q-segments (no max pass:
// |S| small for unmasked, masked -> exp(-1e9)=0; fp32-safe)
// grid (2, NB, NSEG); thread = one float4 of columns
// ============================================================
__global__ void __launch_bounds__(256) k_colpart()
{
    int k  = (blockIdx.x * 256 + threadIdx.x) * 4;
    int b  = blockIdx.y;
    int seg = blockIdx.z;
    const float* Sb = g_S + (size_t)b * NS * NS;
    int q0 = seg * QSEG;

    float4 s = make_float4(0.f, 0.f, 0.f, 0.f);
    #pragma unroll 4
    for (int q = q0; q < q0 + QSEG; q++) {
        float4 v = *(const float4*)&Sb[(size_t)q * NS + k];
        s.x += __expf(v.x);
        s.y += __expf(v.y);
        s.z += __expf(v.z);
        s.w += __expf(v.w);
    }
    *(float4*)&g_psum[((size_t)seg * NB + b) * NS + k] = s;
}

// K3b: combine segments -> 1/colsum
__global__ void __launch_bounds__(256) k_colfin()
{
    int i = blockIdx.x * 256 + threadIdx.x;   // b*NS + k
    float s = 0.f;
    #pragma unroll 8
    for (int seg = 0; seg < NSEG; seg++)
        s += g_psum[(size_t)seg * (NB * NS) + i];
    g_cinv[i] = 1.0f / s;
}

// K3c: prescale V by cinv -> g_Vp  (folds softmax denom into V)
__global__ void __launch_bounds__(256) k_vscale(const float* __restrict__ V)
{
    int p = blockIdx.x * 256 + threadIdx.x;   // float4 index
    int bk = p >> 5;                           // b*NS + k  (ND/4 = 32)
    float c = g_cinv[bk];
    float4 v = ((const float4*)V)[p];
    v.x *= c; v.y *= c; v.z *= c; v.w *= c;
    ((float4*)g_Vp)[p] = v;
}

// ============================================================
// K4: out[b,q,:] = sum_k exp(S[q,k]) * Vp[k,:]
// block 256, tile 64q x 128d, k-chunk 32, thread 4q x 8d.
// Double-buffered: V via cp.async, E via LDG-regs (exp on STS).
// dynamic smem: Ae[2][64][36] | Vs[2][32][128]  (51200 B)
// ============================================================
#define KC 32
#define AE_STRIDE 36
#define AE_BUF (64 * AE_STRIDE)            // 2304 floats
#define VS_OFF (2 * AE_BUF)                // 4608
#define VS_BUF (KC * ND)                   // 4096
#define SMEM_OUT_BYTES ((VS_OFF + 2 * VS_BUF) * 4)   // 51200

__global__ void __launch_bounds__(256) k_out(float* __restrict__ Out)
{
    extern __shared__ float smo[];
    float* Ae = smo;               // [2][64][36]
    float* Vs = smo + VS_OFF;      // [2][32][128]

    int b  = blockIdx.y;
    int q0 = blockIdx.x * 64;
    int t  = threadIdx.x;
    int tx = t & 15;      // d = tx*8
    int ty = t >> 4;      // q rows: ty*4 + qq

    const float* Sb = g_S + ((size_t)b * NS + q0) * NS;
    const float* Vb = g_Vp + (size_t)b * NS * ND;

    // E staging map: p in {t, t+256}: row = p>>3, kg = p&7
    int er_row0 = t >> 3,        er_kg0 = t & 7;
    int er_row1 = (t >> 3) + 32, er_kg1 = t & 7;

    ull acc2[4][4];
    #pragma unroll
    for (int i = 0; i < 4; i++)
        #pragma unroll
        for (int j = 0; j < 4; j++) acc2[i][j] = 0ull;

    // ---- prologue: E chunk0 -> regs, V chunk0 -> cp.async ----
    float4 er0 = *(const float4*)&Sb[(size_t)er_row0 * NS + er_kg0 * 4];
    float4 er1 = *(const float4*)&Sb[(size_t)er_row1 * NS + er_kg1 * 4];
    #pragma unroll
    for (int u = 0; u < 4; u++) {
        int p = t + u * 256;
        int row = p >> 5, cg = p & 31;
        cp16(&Vs[row * ND + cg * 4], &Vb[(size_t)row * ND + cg * 4]);
    }
    CP_COMMIT();

    for (int c = 0; c < NS / KC; c++) {
        int buf = c & 1;
        float* Aeb = Ae + buf * AE_BUF;
        const float* Vsb = Vs + buf * VS_BUF;

        // exp-transform + STS current E regs
        {
            float4 e;
            e.x = __expf(er0.x); e.y = __expf(er0.y);
            e.z = __expf(er0.z); e.w = __expf(er0.w);
            *(float4*)&Aeb[er_row0 * AE_STRIDE + er_kg0 * 4] = e;
            e.x = __expf(er1.x); e.y = __expf(er1.y);
            e.z = __expf(er1.z); e.w = __expf(er1.w);
            *(float4*)&Aeb[er_row1 * AE_STRIDE + er_kg1 * 4] = e;
        }
        // prefetch next chunk
        if (c + 1 < NS / KC) {
            int k0n = (c + 1) * KC;
            er0 = *(const float4*)&Sb[(size_t)er_row0 * NS + k0n + er_kg0 * 4];
            er1 = *(const float4*)&Sb[(size_t)er_row1 * NS + k0n + er_kg1 * 4];
            float* Vsn = Vs + ((c + 1) & 1) * VS_BUF;
            #pragma unroll
            for (int u = 0; u < 4; u++) {
                int p = t + u * 256;
                int row = p >> 5, cg = p & 31;
                cp16(&Vsn[row * ND + cg * 4],
                     &Vb[(size_t)(k0n + row) * ND + cg * 4]);
            }
            CP_COMMIT();
            CP_WAIT1();
        } else {
            CP_WAIT0();
        }
        __syncthreads();

        #pragma unroll
        for (int kk = 0; kk < KC; kk++) {
            ulonglong2 v0 = *(const ulonglong2*)&Vsb[kk * ND + tx * 8];
            ulonglong2 v1 = *(const ulonglong2*)&Vsb[kk * ND + tx * 8 + 4];
            #pragma unroll
            for (int qq = 0; qq < 4; qq++) {
                float a = Aeb[(ty * 4 + qq) * AE_STRIDE + kk];
                ull aa = pack2dup(a);
                fma2(acc2[qq][0], aa, v0.x);
                fma2(acc2[qq][1], aa, v0.y);
                fma2(acc2[qq][2], aa, v1.x);
                fma2(acc2[qq][3], aa, v1.y);
            }
        }
        __syncthreads();
    }

    #pragma unroll
    for (int qq = 0; qq < 4; qq++) {
        float4 o0, o1;
        unpack2(acc2[qq][0], o0.x, o0.y);
        unpack2(acc2[qq][1], o0.z, o0.w);
        unpack2(acc2[qq][2], o1.x, o1.y);
        unpack2(acc2[qq][3], o1.z, o1.w);
        float* op = &Out[(size_t)((b * NS) + q0 + ty * 4 + qq) * ND + tx * 8];
        *(float4*)op = o0;
        *(float4*)(op + 4) = o1;
    }
}

// ============================================================
extern "C" void kernel_launch(void* const* d_in, const int* in_sizes, int n_in,
                              void* d_out, int out_size)
{
    const float* Q   = (const float*)d_in[0];
    const float* K   = (const float*)d_in[1];
    const float* V   = (const float*)d_in[2];
    const int*   VL  = (const int*)d_in[3];
    const float* Wql = (const float*)d_in[4];
    const float* bql = (const float*)d_in[5];
    const float* Wkl = (const float*)d_in[6];
    const float* bkl = (const float*)d_in[7];
    const float* Wqh = (const float*)d_in[8];
    const float* bqh = (const float*)d_in[9];
    const float* Wkh = (const float*)d_in[10];
    const float* bkh = (const float*)d_in[11];
    float* out = (float*)d_out;

    cudaFuncSetAttribute(k_out, cudaFuncAttributeMaxDynamicSharedMemorySize,
                         SMEM_OUT_BYTES);

    k_proj<<<NB * NS, 64>>>(Q, K, Wql, bql, Wkl, bkl, Wqh, bqh, Wkh, bkh);

    dim3 g2(NS / 128, NS / 32, NB);
    k_scores<<<g2, 256>>>(VL);

    dim3 g2b(NS / 8, NB);
    k_topk<<<g2b, 256>>>();

    dim3 g3(2, NB, NSEG);
    k_colpart<<<g3, 256>>>();
    k_colfin<<<(NB * NS) / 256, 256>>>();
    k_vscale<<<(NB * NS * ND) / 4 / 256, 256>>>(V);

    dim3 g4(NS / 64, NB);
    k_out<<<g4, 256, SMEM_OUT_BYTES>>>(out);
}

// round 6
// speedup vs baseline: 1.5716x; 1.2403x over previous
#include <cuda_runtime.h>
#include <cstdint>

#define NB 4
#define NS 2048
#define ND 128
#define NDL 16
#define NTOP 8

#define NSEG 64
#define QSEG (NS / NSEG)   // 32

#define KSPLIT 2
#define KHALF (NS / KSPLIT)   // 1024

typedef unsigned long long ull;

// ---- scratch (device globals; no allocation allowed) ----
__device__ float g_qlow[NB * NS * NDL];
__device__ float g_klow[NB * NS * NDL];
__device__ float g_sh[NB * NS];
__device__ float g_S[(size_t)NB * NS * NS];          // 64 MB corrected scores
__device__ float g_psum[NSEG * NB * NS];             // column partial sums
__device__ float g_cinv[NB * NS];
__device__ float g_po[KSPLIT][NB * NS * ND];         // split-k partial outputs (8 MB)

__device__ __forceinline__ float neg_inf() { return __int_as_float(0xff800000u); }

// ---- packed f32x2 helpers (FFMA2 path; ptxas won't emit this from C++) ----
__device__ __forceinline__ ull pack2(float lo, float hi) {
    ull r;
    asm("mov.b64 %0, {%1, %2};" : "=l"(r) : "f"(lo), "f"(hi));
    return r;
}
__device__ __forceinline__ ull pack2dup(float v) {
    ull r;
    asm("mov.b64 %0, {%1, %1};" : "=l"(r) : "f"(v));
    return r;
}
__device__ __forceinline__ void unpack2(ull v, float& lo, float& hi) {
    asm("mov.b64 {%0, %1}, %2;" : "=f"(lo), "=f"(hi) : "l"(v));
}
__device__ __forceinline__ void fma2(ull& acc, ull a, ull b) {
    asm("fma.rn.f32x2 %0, %1, %2, %0;" : "+l"(acc) : "l"(a), "l"(b));
}

// ============================================================
// K1: low/high projections + per-(b,k) correction scalar sh
// ============================================================
__global__ void __launch_bounds__(64) k_proj(
    const float* __restrict__ Q, const float* __restrict__ K,
    const float* __restrict__ Wql, const float* __restrict__ bql,
    const float* __restrict__ Wkl, const float* __restrict__ bkl,
    const float* __restrict__ Wqh, const float* __restrict__ bqh,
    const float* __restrict__ Wkh, const float* __restrict__ bkh)
{
    int row = blockIdx.x;          // b*NS + i
    int t = threadIdx.x;
    __shared__ float qr[ND];
    __shared__ float kr[ND];
    __shared__ float qh[NDL];
    __shared__ float kh[NDL];

    qr[t]      = Q[(size_t)row * ND + t];
    qr[t + 64] = Q[(size_t)row * ND + t + 64];
    kr[t]      = K[(size_t)row * ND + t];
    kr[t + 64] = K[(size_t)row * ND + t + 64];
    __syncthreads();

    int g = t >> 4, j = t & 15;
    if (g == 0) {
        float a = bql[j];
        #pragma unroll 8
        for (int e = 0; e < ND; e++) a += qr[e] * Wql[e * NDL + j];
        g_qlow[(size_t)row * NDL + j] = a;
    } else if (g == 1) {
        float a = bkl[j];
        #pragma unroll 8
        for (int e = 0; e < ND; e++) a += kr[e] * Wkl[e * NDL + j];
        g_klow[(size_t)row * NDL + j] = a;
    } else if (g == 2) {
        float a = bqh[j];
        #pragma unroll 8
        for (int e = 0; e < ND; e++) a += qr[e] * Wqh[e * NDL + j];
        qh[j] = a;
    } else {
        float a = bkh[j];
        #pragma unroll 8
        for (int e = 0; e < ND; e++) a += kr[e] * Wkh[e * NDL + j];
        kh[j] = a;
    }
    __syncthreads();

    if (t == 0) {
        float s = 0.f;
        #pragma unroll
        for (int j2 = 0; j2 < NDL; j2++) s += qh[j2] * kh[j2];
        g_sh[row] = 0.25f * s;    // scale = 1/sqrt(16)
    }
}

// ============================================================
// K2a: masked low-rank scores -> g_S  (f32x2 packed: 2 q rows per lane)
// block = 256 threads, tile 32 q x 128 k
// ============================================================
__global__ void __launch_bounds__(256) k_scores(const int* __restrict__ VL)
{
    __shared__ __align__(16) float ks[128][20];
    __shared__ __align__(16) float Ss[32][132];
    __shared__ int vls[128];

    int b  = blockIdx.z;
    int q0 = blockIdx.y * 32;
    int k0 = blockIdx.x * 128;
    int t  = threadIdx.x;

    {
        const float4* src = (const float4*)(g_klow + ((size_t)b * NS + k0) * NDL);
        #pragma unroll
        for (int u = 0; u < 2; u++) {
            int p = t + u * 256;
            float4 v = src[p];
            *(float4*)&ks[p >> 2][(p & 3) * 4] = v;
        }
    }
    if (t < 128) {
        int vlc = VL[b * NS + k0 + t];
        vlc = vlc < 0 ? 0 : (vlc > NS - 1 ? NS - 1 : vlc);
        vls[t] = vlc;
    }
    __syncthreads();

    int tq = t >> 4;             // 0..15
    int kg = t & 15;             // 0..15
    int ql0 = tq * 2;
    int qg0 = q0 + ql0, qg1 = qg0 + 1;

    ull qp2[NDL];
    {
        const float4* qp = (const float4*)(g_qlow + ((size_t)b * NS + qg0) * NDL);
        #pragma unroll
        for (int u = 0; u < 4; u++) {
            float4 v = qp[u];       // row 0
            float4 w = qp[u + 4];   // row 1
            qp2[u * 4 + 0] = pack2(v.x, w.x);
            qp2[u * 4 + 1] = pack2(v.y, w.y);
            qp2[u * 4 + 2] = pack2(v.z, w.z);
            qp2[u * 4 + 3] = pack2(v.w, w.w);
        }
    }

    #pragma unroll
    for (int i = 0; i < 8; i++) {
        int kl = kg + 16 * i;
        ull acc = 0ull;
        #pragma unroll
        for (int u = 0; u < 4; u++) {
            float4 kv = *(const float4*)&ks[kl][u * 4];
            fma2(acc, qp2[u * 4 + 0], pack2dup(kv.x));
            fma2(acc, qp2[u * 4 + 1], pack2dup(kv.y));
            fma2(acc, qp2[u * 4 + 2], pack2dup(kv.z));
            fma2(acc, qp2[u * 4 + 3], pack2dup(kv.w));
        }
        float a0, a1;
        unpack2(acc, a0, a1);
        a0 *= 0.25f; a1 *= 0.25f;
        int vlc = vls[kl];
        if (vlc == qg0) a0 += -1e9f;
        if (vlc == qg1) a1 += -1e9f;
        Ss[ql0][kl]     = a0;
        Ss[ql0 + 1][kl] = a1;
    }
    __syncthreads();

    #pragma unroll
    for (int u = 0; u < 4; u++) {
        int p = t + u * 256;
        int row = p >> 5, cg = p & 31;
        float4 v = *(const float4*)&Ss[row][cg * 4];
        *(float4*)(g_S + ((size_t)b * NS + q0 + row) * NS + k0 + cg * 4) = v;
    }
}

// ============================================================
// K2b: per-row top-8 and scatter sh into g_S (round-3 proven version)
// one block (256 threads) per (q, b)
// ============================================================
__global__ void __launch_bounds__(256) k_topk()
{
    int q = blockIdx.x, b = blockIdx.y;
    int t = threadIdx.x;
    __shared__ __align__(16) float wk[NS];
    __shared__ float rv[8];
    __shared__ int ri[8];
    __shared__ int s_mi;
    __shared__ int topIdx[NTOP];

    float* Srow = g_S + ((size_t)b * NS + q) * NS;
    #pragma unroll
    for (int u = 0; u < 2; u++) {
        int p = t + u * 256;
        ((float4*)wk)[p] = ((const float4*)Srow)[p];
    }
    __syncthreads();

    float lv = neg_inf(); int li = 0;
    #pragma unroll
    for (int i = 0; i < 8; i++) {
        int k = t + i * 256;
        float v = wk[k];
        if (v > lv) { lv = v; li = k; }
    }

    for (int r = 0; r < NTOP; r++) {
        float mv = lv; int mi = li;
        #pragma unroll
        for (int o = 16; o > 0; o >>= 1) {
            float ov = __shfl_xor_sync(0xffffffffu, mv, o);
            int   oi = __shfl_xor_sync(0xffffffffu, mi, o);
            if (ov > mv || (ov == mv && oi < mi)) { mv = ov; mi = oi; }
        }
        if ((t & 31) == 0) { rv[t >> 5] = mv; ri[t >> 5] = mi; }
        __syncthreads();
        if (t == 0) {
            #pragma unroll
            for (int w = 1; w < 8; w++)
                if (rv[w] > mv || (rv[w] == mv && ri[w] < mi)) { mv = rv[w]; mi = ri[w]; }
            topIdx[r] = mi;
            s_mi = mi;
        }
        __syncthreads();
        if (r < NTOP - 1) {
            int gm = s_mi;
            if ((gm & 255) == t) {      // only the owner rescans
                wk[gm] = neg_inf();
                lv = neg_inf(); li = 0;
                #pragma unroll
                for (int i = 0; i < 8; i++) {
                    int k = t + i * 256;
                    float v = wk[k];
                    if (v > lv) { lv = v; li = k; }
                }
            }
        }
    }

    if (t < NTOP) {
        int idx = topIdx[t];
        Srow[idx] = g_sh[b * NS + idx];
    }
}

// ============================================================
// K3a: partial column sum of exp over q-segments (no max pass:
// masked -> exp(-1e9)=0; unmasked |S| small; fp32-safe)
// grid (2, NB, NSEG); thread = one float4 of columns
// ============================================================
__global__ void __launch_bounds__(256) k_colpart()
{
    int k  = (blockIdx.x * 256 + threadIdx.x) * 4;
    int b  = blockIdx.y;
    int seg = blockIdx.z;
    const float* Sb = g_S + (size_t)b * NS * NS;
    int q0 = seg * QSEG;

    float4 s = make_float4(0.f, 0.f, 0.f, 0.f);
    #pragma unroll 4
    for (int q = q0; q < q0 + QSEG; q++) {
        float4 v = *(const float4*)&Sb[(size_t)q * NS + k];
        s.x += __expf(v.x);
        s.y += __expf(v.y);
        s.z += __expf(v.z);
        s.w += __expf(v.w);
    }
    *(float4*)&g_psum[((size_t)seg * NB + b) * NS + k] = s;
}

// K3b: combine segments -> 1/colsum
__global__ void __launch_bounds__(256) k_colfin()
{
    int i = blockIdx.x * 256 + threadIdx.x;   // b*NS + k
    float s = 0.f;
    #pragma unroll 8
    for (int seg = 0; seg < NSEG; seg++)
        s += g_psum[(size_t)seg * (NB * NS) + i];
    g_cinv[i] = 1.0f / s;
}

// ============================================================
// K4: split-k partial out[b,q,:] = sum_{k in half z} exp(S)*cinv[k]*V[b,k,:]
// grid (NS/64, NB, KSPLIT); block 256; tile 64q x 128d, k-chunk 32
// As dup-packed (a,a) 64-bit so inner loop has zero MOVs
// ============================================================
__global__ void __launch_bounds__(256) k_out(const float* __restrict__ V)
{
    __shared__ ull As2[64][32];                      // 16 KB
    __shared__ __align__(16) float Vs[32][128];      // 16 KB

    int b  = blockIdx.y;
    int q0 = blockIdx.x * 64;
    int z  = blockIdx.z;
    int t  = threadIdx.x;
    int tx = t & 31;     // d group: d = tx*4
    int ty = t >> 5;     // q group: q = q0 + ty*8 + qq

    const float* Sb = g_S + (size_t)b * NS * NS;
    const float* ci = g_cinv + b * NS;
    const float* Vb = V + (size_t)b * NS * ND;

    ull acc2[8][2];
    #pragma unroll
    for (int i = 0; i < 8; i++) { acc2[i][0] = 0ull; acc2[i][1] = 0ull; }

    int kbeg = z * KHALF, kend = kbeg + KHALF;
    for (int k0 = kbeg; k0 < kend; k0 += 32) {
        __syncthreads();
        // A tile 64x32: exp(S)*cinv dup-packed on load (512 float4, 2/thread)
        #pragma unroll
        for (int u = 0; u < 2; u++) {
            int p = t + u * 256;
            int row = p >> 3, colg = p & 7;
            int kk = k0 + colg * 4;
            float4 s4 = *(const float4*)&Sb[(size_t)(q0 + row) * NS + kk];
            float4 c4 = *(const float4*)&ci[kk];
            float a0 = __expf(s4.x) * c4.x, a1 = __expf(s4.y) * c4.y;
            float a2 = __expf(s4.z) * c4.z, a3 = __expf(s4.w) * c4.w;
            As2[row][colg * 4 + 0] = pack2dup(a0);
            As2[row][colg * 4 + 1] = pack2dup(a1);
            As2[row][colg * 4 + 2] = pack2dup(a2);
            As2[row][colg * 4 + 3] = pack2dup(a3);
        }
        // V tile 32x128 (1024 float4, 4/thread)
        #pragma unroll
        for (int u = 0; u < 4; u++) {
            int p = t + u * 256;
            int row = p >> 5, colg = p & 31;
            *(float4*)&Vs[row][colg * 4] =
                *(const float4*)&Vb[(size_t)(k0 + row) * ND + colg * 4];
        }
        __syncthreads();

        #pragma unroll
        for (int kk = 0; kk < 32; kk++) {
            ulonglong2 vv = *(const ulonglong2*)&Vs[kk][tx * 4];
            #pragma unroll
            for (int qq = 0; qq < 8; qq++) {
                ull aa = As2[ty * 8 + qq][kk];   // LDS64 broadcast
                fma2(acc2[qq][0], aa, vv.x);
                fma2(acc2[qq][1], aa, vv.y);
            }
        }
    }

    float* po = g_po[z];
    #pragma unroll
    for (int qq = 0; qq < 8; qq++) {
        float4 o;
        unpack2(acc2[qq][0], o.x, o.y);
        unpack2(acc2[qq][1], o.z, o.w);
        *(float4*)&po[(size_t)((b * NS) + q0 + ty * 8 + qq) * ND + tx * 4] = o;
    }
}

// K5: add the two split-k halves -> final out
__global__ void __launch_bounds__(256) k_add(float* __restrict__ Out)
{
    int p = blockIdx.x * 256 + threadIdx.x;   // float4 index
    float4 a = ((const float4*)g_po[0])[p];
    float4 c = ((const float4*)g_po[1])[p];
    a.x += c.x; a.y += c.y; a.z += c.z; a.w += c.w;
    ((float4*)Out)[p] = a;
}

// ============================================================
extern "C" void kernel_launch(void* const* d_in, const int* in_sizes, int n_in,
                              void* d_out, int out_size)
{
    const float* Q   = (const float*)d_in[0];
    const float* K   = (const float*)d_in[1];
    const float* V   = (const float*)d_in[2];
    const int*   VL  = (const int*)d_in[3];
    const float* Wql = (const float*)d_in[4];
    const float* bql = (const float*)d_in[5];
    const float* Wkl = (const float*)d_in[6];
    const float* bkl = (const float*)d_in[7];
    const float* Wqh = (const float*)d_in[8];
    const float* bqh = (const float*)d_in[9];
    const float* Wkh = (const float*)d_in[10];
    const float* bkh = (const float*)d_in[11];
    float* out = (float*)d_out;

    k_proj<<<NB * NS, 64>>>(Q, K, Wql, bql, Wkl, bkl, Wqh, bqh, Wkh, bkh);

    dim3 g2(NS / 128, NS / 32, NB);
    k_scores<<<g2, 256>>>(VL);

    dim3 g2b(NS, NB);
    k_topk<<<g2b, 256>>>();

    dim3 g3(2, NB, NSEG);
    k_colpart<<<g3, 256>>>();
    k_colfin<<<(NB * NS) / 256, 256>>>();

    dim3 g4(NS / 64, NB, KSPLIT);
    k_out<<<g4, 256>>>(V);

    k_add<<<(NB * NS * ND) / 4 / 256, 256>>>(out);
}